// round 2
// baseline (speedup 1.0000x reference)
#include <cuda_runtime.h>
#include <math.h>

// Problem constants
#define B   32
#define T   256
#define D   256
#define H   1024
#define G3  3072          // 3*H
#define OO  256           // output classes
#define ALPHA 0.001f
#define ONEMA 0.999f

#define CK  256           // k-chunk per block
#define KH_CHUNKS 4       // hidden chunks (1024/256)
#define KS0 5             // layer0: 1024 hidden + 256 x
#define KS1 8             // layer1: 1024 hidden + 1024 x

// ---------------- scratch (static device globals; allocation-free) -------------
__device__ float g_WT0[(H + D) * G3];      // 1280 x 3072 k-major  (15.7 MB)
__device__ float g_WT1[(H + H) * G3];      // 2048 x 3072 k-major  (25.2 MB)
__device__ float g_o0[T * B * H];          // layer0 event outputs (33.5 MB)
__device__ float g_state_c[2][B * H];
__device__ float g_state_o[2][B * H];
__device__ float g_state_i[2][B * G3];
__device__ float g_part[KS1 * B * G3];     // K-split partial sums (3 MB)
__device__ unsigned g_cnt[32];             // per-jtile arrival counters (self-resetting)

__device__ __forceinline__ float sigmoidf_(float x) { return 1.0f / (1.0f + expf(-x)); }

// ---------------- weight pack: dst[k][col] = src[col][k] -----------------------
// src: (3072, K) row-major. dstSel: 0 -> g_WT0, 1 -> g_WT1. Row offset for x part.
__global__ void pack_kernel(const float* __restrict__ src, int dstSel, int K, int rowOff) {
    __shared__ float tile[32][33];
    float* dst = dstSel ? g_WT1 : g_WT0;
    int kBase = blockIdx.x * 32;
    int colBase = blockIdx.y * 32;
    int tx = threadIdx.x, ty = threadIdx.y;   // (32, 8)
#pragma unroll
    for (int i = 0; i < 32; i += 8) {
        int col = colBase + ty + i;
        tile[ty + i][tx] = src[(size_t)col * K + kBase + tx];
    }
    __syncthreads();
#pragma unroll
    for (int i = 0; i < 32; i += 8) {
        int k = kBase + ty + i;
        dst[(size_t)(k + rowOff) * G3 + colBase + tx] = tile[tx][ty + i];
    }
}

// ---------------- zero initial state -------------------------------------------
__global__ void init_state_kernel() {
    int idx = blockIdx.x * blockDim.x + threadIdx.x;
    if (idx < B * H) { g_state_c[0][idx] = 0.0f; g_state_o[0][idx] = 0.0f; }
    if (idx < B * G3) g_state_i[0][idx] = 0.0f;
}

// ---------------- one recurrent step (fused GEMM + update) ---------------------
// grid: (32 j-tiles, KS k-splits), 256 threads.
// Thread tile: 4 consecutive j (float4) x 1 batch x 3 gates.
template <int LAYER>
__global__ __launch_bounds__(256) void step_kernel(
    int t, int pp,
    const float* __restrict__ xb,        // layer0: x (B,T,D). layer1: unused
    const float* __restrict__ bias,
    const float* __restrict__ thr_raw,
    float* __restrict__ hs, float* __restrict__ cs,
    float* __restrict__ os, float* __restrict__ is_)
{
    const float* __restrict__ WT = (LAYER == 0) ? g_WT0 : g_WT1;
    const int KS = gridDim.y;
    const int ks = blockIdx.y;
    const int jtile = blockIdx.x;
    const int jbase = jtile * 32;
    const int k0 = ks * CK;
    const int tid = threadIdx.x;

    const float* __restrict__ cP = g_state_c[pp];
    const float* __restrict__ oP = g_state_o[pp];
    const float* __restrict__ iP = g_state_i[pp];
    float* __restrict__ cN = g_state_c[pp ^ 1];
    float* __restrict__ oN = g_state_o[pp ^ 1];
    float* __restrict__ iN = g_state_i[pp ^ 1];

    __shared__ float sh_act[B][CK + 1];

    // ---- stage activation chunk (hidden = o*c, or layer input) ----
    const bool isHidden = (ks < KH_CHUNKS);
    for (int idx = tid; idx < B * CK; idx += 256) {
        int b = idx >> 8;
        int kk = idx & 255;
        float v;
        if (isHidden) {
            int kg = k0 + kk;
            v = oP[b * H + kg] * cP[b * H + kg];
        } else {
            int kx = k0 - H + kk;
            if (LAYER == 0) v = xb[b * (T * D) + t * D + kx];
            else            v = g_o0[t * (B * H) + b * H + kx];
        }
        sh_act[b][kk] = v;
    }
    __syncthreads();

    // ---- GEMM partial: 4j x 1b x 3 gates per thread ----
    const int jl = tid & 7;          // 0..7  -> j = jbase + jl*4 .. +3
    const int b  = tid >> 3;         // 0..31
    const float* wp = WT + (size_t)k0 * G3 + jbase + jl * 4;
    const float* __restrict__ arow = sh_act[b];

    float4 aU = {0.f,0.f,0.f,0.f}, aR = {0.f,0.f,0.f,0.f}, aC = {0.f,0.f,0.f,0.f};
#pragma unroll 4
    for (int kk = 0; kk < CK; kk++) {
        float a = arow[kk];
        float4 wu = *(const float4*)(wp);
        float4 wr = *(const float4*)(wp + H);
        float4 wc = *(const float4*)(wp + 2 * H);
        aU.x += wu.x * a; aU.y += wu.y * a; aU.z += wu.z * a; aU.w += wu.w * a;
        aR.x += wr.x * a; aR.y += wr.y * a; aR.z += wr.z * a; aR.w += wr.w * a;
        aC.x += wc.x * a; aC.y += wc.y * a; aC.z += wc.z * a; aC.w += wc.w * a;
        wp += G3;
    }

    float* pb = g_part + ((size_t)(ks * B + b) * 3) * H + jbase + jl * 4;
    *(float4*)(pb)         = aU;
    *(float4*)(pb + H)     = aR;
    *(float4*)(pb + 2 * H) = aC;

    __threadfence();
    __syncthreads();
    __shared__ unsigned s_old;
    if (tid == 0) s_old = atomicAdd(&g_cnt[jtile], 1u);
    __syncthreads();
    if (s_old != (unsigned)(KS - 1)) return;   // not the last-arriving block
    __threadfence();

    // ---- finisher: reduce partials + elementwise EGRU update ----
    float4 lU = {0,0,0,0}, lR = {0,0,0,0}, lHC = {0,0,0,0}, lXC = {0,0,0,0};
    for (int s = 0; s < KS; s++) {
        const float* q = g_part + ((size_t)(s * B + b) * 3) * H + jbase + jl * 4;
        float4 u4 = *(const float4*)(q);
        float4 r4 = *(const float4*)(q + H);
        float4 c4 = *(const float4*)(q + 2 * H);
        lU.x += u4.x; lU.y += u4.y; lU.z += u4.z; lU.w += u4.w;
        lR.x += r4.x; lR.y += r4.y; lR.z += r4.z; lR.w += r4.w;
        if (s < KH_CHUNKS) { lHC.x += c4.x; lHC.y += c4.y; lHC.z += c4.z; lHC.w += c4.w; }
        else               { lXC.x += c4.x; lXC.y += c4.y; lXC.z += c4.z; lXC.w += c4.w; }
    }
    float LU[4] = {lU.x, lU.y, lU.z, lU.w};
    float LR[4] = {lR.x, lR.y, lR.z, lR.w};
    float LHC[4] = {lHC.x, lHC.y, lHC.z, lHC.w};
    float LXC[4] = {lXC.x, lXC.y, lXC.z, lXC.w};

#pragma unroll
    for (int i = 0; i < 4; i++) {
        int jj = jbase + jl * 4 + i;
        float iu = iP[b * G3 + jj];
        float ir = iP[b * G3 + H + jj];
        float ic = iP[b * G3 + 2 * H + jj];

        float niu = ALPHA * iu + ONEMA * (LU[i] + bias[jj]);
        float u = sigmoidf_(niu);
        float nir = ALPHA * ir + ONEMA * (LR[i] + bias[H + jj]);
        float r = sigmoidf_(nir);
        float nic = ALPHA * ic + ONEMA * (LXC[i] + r * LHC[i] + bias[2 * H + jj]);
        float z = tanhf(nic);

        float th = sigmoidf_(thr_raw[jj]);
        float cp = cP[b * H + jj];
        float op = oP[b * H + jj];
        float creset = cp - op * th;
        float nc = (1.0f - u) * creset + u * z;
        float diff = nc - th;
        float no = (diff > 0.0f) ? 1.0f : 0.0f;
        float nh = no * nc;

        cN[b * H + jj] = nc;
        oN[b * H + jj] = no;
        iN[b * G3 + jj] = niu;
        iN[b * G3 + H + jj] = nir;
        iN[b * G3 + 2 * H + jj] = nic;

        if (LAYER == 0) {
            g_o0[t * (B * H) + b * H + jj] = no;
        } else {
            int hoff = t * (B * H) + b * H + jj;
            hs[hoff] = nh;
            cs[hoff] = nc;
            os[hoff] = no;
            int ioff = t * (B * G3) + b * G3 + jj;
            is_[ioff] = niu;
            is_[ioff + H] = nir;
            is_[ioff + 2 * H] = nic;
        }
    }
    if (tid == 0) g_cnt[jtile] = 0;   // reset for next step (kernel-boundary ordered)
}

// ---------------- softmax head -------------------------------------------------
__global__ void head_kernel(const float* __restrict__ hLast,
                            const float* __restrict__ w_out,
                            const float* __restrict__ b_out,
                            float* __restrict__ pred)
{
    __shared__ float sh_h[H];
    __shared__ float red[OO];
    int b = blockIdx.x, tid = threadIdx.x;    // 256 threads, one per output col
    for (int i = tid; i < H; i += OO) sh_h[i] = hLast[b * H + i];
    __syncthreads();

    float acc = 0.0f;
    const float* w = w_out + (size_t)tid * H;
#pragma unroll 4
    for (int k = 0; k < H; k++) acc += w[k] * sh_h[k];
    float logit = acc + b_out[tid];

    red[tid] = logit; __syncthreads();
    for (int s = 128; s > 0; s >>= 1) { if (tid < s) red[tid] = fmaxf(red[tid], red[tid + s]); __syncthreads(); }
    float mx = red[0]; __syncthreads();
    float e = expf(logit - mx);
    red[tid] = e; __syncthreads();
    for (int s = 128; s > 0; s >>= 1) { if (tid < s) red[tid] += red[tid + s]; __syncthreads(); }
    float sum = red[0];
    pred[b * OO + tid] = e / sum;
}

// ---------------- launch -------------------------------------------------------
extern "C" void kernel_launch(void* const* d_in, const int* in_sizes, int n_in,
                              void* d_out, int out_size) {
    const float* x     = (const float*)d_in[0];
    const float* w_ih0 = (const float*)d_in[1];
    const float* w_hh0 = (const float*)d_in[2];
    const float* bias0 = (const float*)d_in[3];
    const float* thr0  = (const float*)d_in[4];
    const float* w_ih1 = (const float*)d_in[6];
    const float* w_hh1 = (const float*)d_in[7];
    const float* bias1 = (const float*)d_in[8];
    const float* thr1  = (const float*)d_in[9];
    const float* w_out = (const float*)d_in[11];
    const float* b_out = (const float*)d_in[12];

    float* out = (float*)d_out;
    float* pred = out;                         //   8192
    float* hs = out + B * OO;                  //   T*B*H
    float* cs = hs + T * B * H;
    float* os = cs + T * B * H;
    float* is_ = os + T * B * H;

    dim3 tpt(32, 8);
    // layer 0: WT0 = [w_hh0 (k<1024) ; w_ih0 (k in 1024..1279)], k-major
    pack_kernel<<<dim3(H / 32, G3 / 32), tpt>>>(w_hh0, 0, H, 0);
    pack_kernel<<<dim3(D / 32, G3 / 32), tpt>>>(w_ih0, 0, D, H);
    // layer 1: WT1 = [w_hh1 ; w_ih1]
    pack_kernel<<<dim3(H / 32, G3 / 32), tpt>>>(w_hh1, 1, H, 0);
    pack_kernel<<<dim3(H / 32, G3 / 32), tpt>>>(w_ih1, 1, H, H);

    init_state_kernel<<<(B * G3 + 255) / 256, 256>>>();
    for (int t = 0; t < T; t++) {
        step_kernel<0><<<dim3(32, KS0), 256>>>(t, t & 1, x, bias0, thr0,
                                               nullptr, nullptr, nullptr, nullptr);
    }
    init_state_kernel<<<(B * G3 + 255) / 256, 256>>>();
    for (int t = 0; t < T; t++) {
        step_kernel<1><<<dim3(32, KS1), 256>>>(t, t & 1, nullptr, bias1, thr1,
                                               hs, cs, os, is_);
    }
    head_kernel<<<B, OO>>>(hs + (T - 1) * B * H, w_out, b_out, pred);
}

// round 3
// speedup vs baseline: 1.0875x; 1.0875x over previous
#include <cuda_runtime.h>
#include <math.h>

// Problem constants
#define B    32
#define T    256
#define D    256
#define HID  1024
#define G3   3072
#define OO   256
#define ALPHA 0.001f
#define ONEMA 0.999f

#define NBLK 128      // persistent grid: 32 jtiles x 4 kchunks (all resident, <=148 SMs)
#define KCH  4

// ---------------- static device scratch (allocation-free) ----------------
__device__ float g_WT0[(HID + D) * G3];      // 1280 x 3072 k-major
__device__ float g_WT1[(HID + HID) * G3];    // 2048 x 3072 k-major
__device__ float g_o0[(size_t)T * B * HID];  // layer0 event outputs
__device__ float g_sc[B * HID];              // c state (single buffer)
__device__ float g_so[B * HID];              // o state
__device__ float g_si[B * G3];               // i state
__device__ float g_part[KCH * B * 4 * HID];  // partials: u, r, cHid, cX
__device__ unsigned g_bar_cnt;
__device__ volatile unsigned g_bar_gen;

__device__ __forceinline__ float sigmoidf_(float v) { return 1.0f / (1.0f + expf(-v)); }

// ---------------- grid-wide barrier (all NBLK blocks resident) ----------------
__device__ __forceinline__ void gbar(unsigned target) {
    __syncthreads();
    if (threadIdx.x == 0) {
        __threadfence();
        unsigned old = atomicAdd(&g_bar_cnt, 1u);
        if (old == NBLK - 1u) {
            g_bar_cnt = 0u;
            __threadfence();
            g_bar_gen = target;
        } else {
            while (g_bar_gen != target) { }
        }
        __threadfence();
    }
    __syncthreads();
}

// ---------------- weight pack: dst[k][col] = src[col][k] ----------------
__global__ void pack_kernel(const float* __restrict__ src, int dstSel, int K, int rowOff) {
    __shared__ float tile[32][33];
    float* dst = dstSel ? g_WT1 : g_WT0;
    int kBase = blockIdx.x * 32;
    int colBase = blockIdx.y * 32;
    int tx = threadIdx.x, ty = threadIdx.y;   // (32, 8)
#pragma unroll
    for (int i = 0; i < 32; i += 8) {
        int col = colBase + ty + i;
        tile[ty + i][tx] = src[(size_t)col * K + kBase + tx];
    }
    __syncthreads();
#pragma unroll
    for (int i = 0; i < 32; i += 8) {
        int k = kBase + ty + i;
        dst[(size_t)(k + rowOff) * G3 + colBase + tx] = tile[tx][ty + i];
    }
}

// ---------------- state + barrier init ----------------
__global__ void init_state_kernel() {
    int idx = blockIdx.x * blockDim.x + threadIdx.x;
    if (idx < B * HID) { g_sc[idx] = 0.0f; g_so[idx] = 0.0f; }
    if (idx < B * G3) g_si[idx] = 0.0f;
    if (idx == 0) { g_bar_cnt = 0u; g_bar_gen = 0u; }
}

// ---------------- persistent scan kernel (one per layer) ----------------
// grid = 128 blocks: bid>>2 = jtile (32 j each), bid&3 = kchunk. 256 threads.
// Phase A: GEMM partials for (jtile, kchunk). Phase B: 1 element/thread update.
template <int LAYER>
__global__ __launch_bounds__(256, 1) void scan_kernel(
    const float* __restrict__ x,          // layer0: input x (B,T,D); layer1: unused
    const float* __restrict__ bias,
    const float* __restrict__ thr_raw,
    float* __restrict__ hs, float* __restrict__ cs,
    float* __restrict__ os, float* __restrict__ is_)
{
    constexpr int CK   = (LAYER == 0) ? 320 : 512;   // K total 1280 / 2048
    constexpr int NSTG = (LAYER == 0) ? 1 : 2;       // smem stages per chunk
    constexpr int SLEN = (LAYER == 0) ? 320 : 256;   // k per stage
    const float* __restrict__ WT = (LAYER == 0) ? g_WT0 : g_WT1;

    __shared__ float s_act[SLEN * 33];               // [kk][b] padded (bank-safe)

    const int tid = threadIdx.x;
    const int kc  = blockIdx.x & 3;
    const int jt  = blockIdx.x >> 2;
    const int jbase = jt * 32;
    const int k0  = kc * CK;
    const int jl  = tid & 7;          // 0..7 -> 4 consecutive j (float4)
    const int bb  = tid >> 3;         // 0..31 batch

    // finisher mapping: one (b, j) element per thread
    const int fidx = blockIdx.x * 256 + tid;         // 0..32767 = B*HID
    const int fb = fidx >> 10;
    const int fj = fidx & 1023;
    const float thr = sigmoidf_(thr_raw[fj]);
    const float bU = bias[fj], bR = bias[HID + fj], bC = bias[2 * HID + fj];

    unsigned gen = 0;

    for (int t = 0; t < T; t++) {
        // ================= Phase A: stage activations + GEMM partial =================
        float4 aU  = {0,0,0,0}, aR  = {0,0,0,0};
        float4 aCH = {0,0,0,0}, aCX = {0,0,0,0};
        const float* wbase = WT + (size_t)k0 * G3 + jbase + jl * 4;

        for (int st = 0; st < NSTG; st++) {
            const int sb = k0 + st * SLEN;           // global k of stage start
            for (int idx = tid; idx < B * SLEN; idx += 256) {
                int b_ = idx / SLEN;
                int kk = idx - b_ * SLEN;
                int kg = sb + kk;
                float v;
                if (kg < HID) {
                    v = g_so[b_ * HID + kg] * g_sc[b_ * HID + kg];
                } else {
                    int kx = kg - HID;
                    if (LAYER == 0) v = x[(size_t)b_ * (T * D) + t * D + kx];
                    else            v = g_o0[(size_t)t * (B * HID) + b_ * HID + kx];
                }
                s_act[kk * 33 + b_] = v;
            }
            __syncthreads();

            int hEnd = HID - sb;
            if (hEnd < 0) hEnd = 0;
            if (hEnd > SLEN) hEnd = SLEN;
            const float* wp = wbase + (size_t)(st * SLEN) * G3;

            int kk = 0;
#pragma unroll 4
            for (; kk < hEnd; kk++) {                // hidden part -> cHid
                float a = s_act[kk * 33 + bb];
                float4 wu = *(const float4*)(wp);
                float4 wr = *(const float4*)(wp + HID);
                float4 wc = *(const float4*)(wp + 2 * HID);
                aU.x  = fmaf(wu.x, a, aU.x);  aU.y  = fmaf(wu.y, a, aU.y);
                aU.z  = fmaf(wu.z, a, aU.z);  aU.w  = fmaf(wu.w, a, aU.w);
                aR.x  = fmaf(wr.x, a, aR.x);  aR.y  = fmaf(wr.y, a, aR.y);
                aR.z  = fmaf(wr.z, a, aR.z);  aR.w  = fmaf(wr.w, a, aR.w);
                aCH.x = fmaf(wc.x, a, aCH.x); aCH.y = fmaf(wc.y, a, aCH.y);
                aCH.z = fmaf(wc.z, a, aCH.z); aCH.w = fmaf(wc.w, a, aCH.w);
                wp += G3;
            }
#pragma unroll 4
            for (; kk < SLEN; kk++) {                // input part -> cX
                float a = s_act[kk * 33 + bb];
                float4 wu = *(const float4*)(wp);
                float4 wr = *(const float4*)(wp + HID);
                float4 wc = *(const float4*)(wp + 2 * HID);
                aU.x  = fmaf(wu.x, a, aU.x);  aU.y  = fmaf(wu.y, a, aU.y);
                aU.z  = fmaf(wu.z, a, aU.z);  aU.w  = fmaf(wu.w, a, aU.w);
                aR.x  = fmaf(wr.x, a, aR.x);  aR.y  = fmaf(wr.y, a, aR.y);
                aR.z  = fmaf(wr.z, a, aR.z);  aR.w  = fmaf(wr.w, a, aR.w);
                aCX.x = fmaf(wc.x, a, aCX.x); aCX.y = fmaf(wc.y, a, aCX.y);
                aCX.z = fmaf(wc.z, a, aCX.z); aCX.w = fmaf(wc.w, a, aCX.w);
                wp += G3;
            }
            __syncthreads();
        }

        float* pb = g_part + ((size_t)(kc * B + bb) * 4) * HID + jbase + jl * 4;
        *(float4*)(pb)           = aU;
        *(float4*)(pb + HID)     = aR;
        *(float4*)(pb + 2 * HID) = aCH;
        *(float4*)(pb + 3 * HID) = aCX;

        gbar(++gen);

        // ================= Phase B: elementwise EGRU update (1 elem/thread) =========
        {
            float su = 0.f, sr = 0.f, sch = 0.f, scx = 0.f;
#pragma unroll
            for (int s = 0; s < KCH; s++) {
                const float* q = g_part + ((size_t)(s * B + fb) * 4) * HID + fj;
                su  += q[0];
                sr  += q[HID];
                sch += q[2 * HID];
                scx += q[3 * HID];
            }
            float iu = g_si[fb * G3 + fj];
            float ir = g_si[fb * G3 + HID + fj];
            float ic = g_si[fb * G3 + 2 * HID + fj];

            float niu = ALPHA * iu + ONEMA * (su + bU);
            float u = sigmoidf_(niu);
            float nir = ALPHA * ir + ONEMA * (sr + bR);
            float r = sigmoidf_(nir);
            float nic = ALPHA * ic + ONEMA * (scx + r * sch + bC);
            float z = tanhf(nic);

            float cp = g_sc[fb * HID + fj];
            float op = g_so[fb * HID + fj];
            float creset = cp - op * thr;
            float nc = (1.0f - u) * creset + u * z;
            float no = (nc - thr > 0.0f) ? 1.0f : 0.0f;

            g_sc[fb * HID + fj] = nc;
            g_so[fb * HID + fj] = no;
            g_si[fb * G3 + fj] = niu;
            g_si[fb * G3 + HID + fj] = nir;
            g_si[fb * G3 + 2 * HID + fj] = nic;

            if (LAYER == 0) {
                g_o0[(size_t)t * (B * HID) + fb * HID + fj] = no;
            } else {
                size_t ho = (size_t)t * (B * HID) + fb * HID + fj;
                hs[ho] = no * nc;
                cs[ho] = nc;
                os[ho] = no;
                size_t io = (size_t)t * (B * G3) + fb * G3 + fj;
                is_[io] = niu;
                is_[io + HID] = nir;
                is_[io + 2 * HID] = nic;
            }
        }
        gbar(++gen);
    }
}

// ---------------- softmax head ----------------
__global__ void head_kernel(const float* __restrict__ hLast,
                            const float* __restrict__ w_out,
                            const float* __restrict__ b_out,
                            float* __restrict__ pred)
{
    __shared__ float sh_h[HID];
    __shared__ float red[OO];
    int b = blockIdx.x, tid = threadIdx.x;    // 256 threads, one per output col
    for (int i = tid; i < HID; i += OO) sh_h[i] = hLast[b * HID + i];
    __syncthreads();

    float acc = 0.0f;
    const float* w = w_out + (size_t)tid * HID;
#pragma unroll 4
    for (int k = 0; k < HID; k++) acc += w[k] * sh_h[k];
    float logit = acc + b_out[tid];

    red[tid] = logit; __syncthreads();
    for (int s = 128; s > 0; s >>= 1) { if (tid < s) red[tid] = fmaxf(red[tid], red[tid + s]); __syncthreads(); }
    float mx = red[0]; __syncthreads();
    float e = expf(logit - mx);
    red[tid] = e; __syncthreads();
    for (int s = 128; s > 0; s >>= 1) { if (tid < s) red[tid] += red[tid + s]; __syncthreads(); }
    float sum = red[0];
    pred[b * OO + tid] = e / sum;
}

// ---------------- launch ----------------
extern "C" void kernel_launch(void* const* d_in, const int* in_sizes, int n_in,
                              void* d_out, int out_size) {
    const float* x     = (const float*)d_in[0];
    const float* w_ih0 = (const float*)d_in[1];
    const float* w_hh0 = (const float*)d_in[2];
    const float* bias0 = (const float*)d_in[3];
    const float* thr0  = (const float*)d_in[4];
    const float* w_ih1 = (const float*)d_in[6];
    const float* w_hh1 = (const float*)d_in[7];
    const float* bias1 = (const float*)d_in[8];
    const float* thr1  = (const float*)d_in[9];
    const float* w_out = (const float*)d_in[11];
    const float* b_out = (const float*)d_in[12];

    float* out  = (float*)d_out;
    float* pred = out;
    float* hs   = out + B * OO;
    float* cs   = hs + (size_t)T * B * HID;
    float* os   = cs + (size_t)T * B * HID;
    float* is_  = os + (size_t)T * B * HID;

    dim3 tpt(32, 8);
    // layer 0: WT0 = [w_hh0 (k<1024) ; w_ih0 (k 1024..1279)], k-major
    pack_kernel<<<dim3(HID / 32, G3 / 32), tpt>>>(w_hh0, 0, HID, 0);
    pack_kernel<<<dim3(D / 32, G3 / 32), tpt>>>(w_ih0, 0, D, HID);
    // layer 1: WT1 = [w_hh1 ; w_ih1]
    pack_kernel<<<dim3(HID / 32, G3 / 32), tpt>>>(w_hh1, 1, HID, 0);
    pack_kernel<<<dim3(HID / 32, G3 / 32), tpt>>>(w_ih1, 1, HID, HID);

    init_state_kernel<<<(B * G3 + 255) / 256, 256>>>();
    scan_kernel<0><<<NBLK, 256>>>(x, bias0, thr0, nullptr, nullptr, nullptr, nullptr);

    init_state_kernel<<<(B * G3 + 255) / 256, 256>>>();
    scan_kernel<1><<<NBLK, 256>>>(nullptr, bias1, thr1, hs, cs, os, is_);

    head_kernel<<<B, OO>>>(hs + (size_t)(T - 1) * B * HID, w_out, b_out, pred);
}

// round 4
// speedup vs baseline: 1.5500x; 1.4253x over previous
#include <cuda_runtime.h>
#include <math.h>

// Problem constants
#define B    32
#define T    256
#define D    256
#define HID  1024
#define G3   3072
#define OO   256
#define ALPHA 0.001f
#define ONEMA 0.999f

#define NBLK 128          // 8 jtiles x 16 kchunks; all resident (<=148 SMs)
#define THR  512          // 16 warps
#define KC   16

typedef unsigned long long u64;

// ---------------- static device scratch (allocation-free) ----------------
__device__ float g_WT0[(HID + D) * G3];        // 1280 x 3072 k-major
__device__ float g_WT1[(HID + HID) * G3];      // 2048 x 3072 k-major
__device__ float g_o0[(size_t)T * HID * B];    // layer0 events, [t][j][b]
__device__ float g_sc[HID * B];                // c state, [j][b]
__device__ float g_so[HID * B];                // o state, [j][b]
__device__ float g_si[G3 * B];                 // i state, [col][b]
__device__ float g_part[KC * 4 * HID * B];     // partials [kc][plane:u,r,ch,cx][j][b]
__device__ unsigned g_bar_cnt;
__device__ volatile unsigned g_bar_gen;

__device__ __forceinline__ float sigmoidf_(float v) { return 1.0f / (1.0f + expf(-v)); }

__device__ __forceinline__ void ffma2(u64& d, u64 a, u64 b) {
    asm("fma.rn.f32x2 %0, %1, %2, %0;" : "+l"(d) : "l"(a), "l"(b));
}
__device__ __forceinline__ u64 packdup(float a) {
    u64 r; unsigned ua = __float_as_uint(a);
    asm("mov.b64 %0, {%1, %1};" : "=l"(r) : "r"(ua));
    return r;
}
__device__ __forceinline__ void unpack2(u64 v, float& lo, float& hi) {
    unsigned l, h;
    asm("mov.b64 {%0, %1}, %2;" : "=r"(l), "=r"(h) : "l"(v));
    lo = __uint_as_float(l); hi = __uint_as_float(h);
}
__device__ __forceinline__ void ldw2(u64& a, u64& b, const float* p) {
    asm("ld.global.nc.v2.b64 {%0, %1}, [%2];" : "=l"(a), "=l"(b) : "l"(p));
}

// ---------------- grid-wide barrier (all NBLK blocks resident) ----------------
__device__ __forceinline__ void gbar(unsigned target) {
    __syncthreads();
    if (threadIdx.x == 0) {
        __threadfence();
        unsigned old = atomicAdd(&g_bar_cnt, 1u);
        if (old == NBLK - 1u) {
            g_bar_cnt = 0u;
            __threadfence();
            g_bar_gen = target;
        } else {
            while (g_bar_gen != target) { }
        }
        __threadfence();
    }
    __syncthreads();
}

// ---------------- weight pack: dst[k][col] = src[col][k] ----------------
__global__ void pack_kernel(const float* __restrict__ src, int dstSel, int K, int rowOff) {
    __shared__ float tile[32][33];
    float* dst = dstSel ? g_WT1 : g_WT0;
    int kBase = blockIdx.x * 32;
    int colBase = blockIdx.y * 32;
    int tx = threadIdx.x, ty = threadIdx.y;   // (32, 8)
#pragma unroll
    for (int i = 0; i < 32; i += 8) {
        int col = colBase + ty + i;
        tile[ty + i][tx] = src[(size_t)col * K + kBase + tx];
    }
    __syncthreads();
#pragma unroll
    for (int i = 0; i < 32; i += 8) {
        int k = kBase + ty + i;
        dst[(size_t)(k + rowOff) * G3 + colBase + tx] = tile[tx][ty + i];
    }
}

// ---------------- state + barrier init ----------------
__global__ void init_state_kernel() {
    int idx = blockIdx.x * blockDim.x + threadIdx.x;
    if (idx < HID * B) { g_sc[idx] = 0.0f; g_so[idx] = 0.0f; }
    if (idx < G3 * B) g_si[idx] = 0.0f;
    if (idx == 0) { g_bar_cnt = 0u; g_bar_gen = 0u; }
}

// ---------------- persistent scan kernel ----------------
// grid = 128 blocks (bid>>4 = jtile of 128 j, bid&15 = kchunk), 512 threads.
// Phase A: lane=batch GEMM partial with f32x2 FMAs. Phase B: 256 thr/block update.
template <int LAYER>
__global__ __launch_bounds__(THR, 1) void scan_kernel(
    const float* __restrict__ x,          // layer0 input (B,T,D); layer1 unused
    const float* __restrict__ bias,
    const float* __restrict__ thr_raw,
    float* __restrict__ hs, float* __restrict__ cs,
    float* __restrict__ os, float* __restrict__ is_)
{
    constexpr int CK    = (LAYER == 0) ? 80 : 128;     // K tot 1280 / 2048, 16 chunks
    constexpr int CH_HI = (LAYER == 0) ? 13 : 8;       // chunks with hidden contribution
    constexpr int CX_LO = (LAYER == 0) ? 12 : 8;       // chunks with x contribution
    const float* __restrict__ WT = (LAYER == 0) ? g_WT0 : g_WT1;

    __shared__ float s_act[CK * 32];                   // [kk][b]

    const int tid  = threadIdx.x;
    const int lane = tid & 31;                         // = batch
    const int wrp  = tid >> 5;                         // 0..15
    const int kc   = blockIdx.x & 15;
    const int jt   = blockIdx.x >> 4;
    const int k0   = kc * CK;
    const int j0   = jt * 128 + wrp * 8;               // 8 j per warp

    int hEnd = HID - k0;                               // rows in chunk that are hidden
    if (hEnd < 0) hEnd = 0;
    if (hEnd > CK) hEnd = CK;

    // phase-B mapping: 256 threads/block, one (b, j) each
    const int fidx = blockIdx.x * 256 + tid;           // < 32768 when tid<256
    const int fb = fidx & 31;
    const int fj = fidx >> 5;
    float thr = 0.f, bU = 0.f, bR = 0.f, bC = 0.f;
    if (tid < 256) {
        thr = sigmoidf_(thr_raw[fj]);
        bU = bias[fj]; bR = bias[HID + fj]; bC = bias[2 * HID + fj];
    }

    unsigned gen = 0;

    for (int t = 0; t < T; t++) {
        // ================= Phase A: stage activations =================
        for (int idx = tid; idx < CK * 32; idx += THR) {
            int kk = idx >> 5;
            int b_ = idx & 31;
            int kg = k0 + kk;
            float v;
            if (kg < HID) {
                v = g_so[kg * 32 + b_] * g_sc[kg * 32 + b_];
            } else {
                int kx = kg - HID;
                if (LAYER == 0) v = x[(size_t)b_ * (T * D) + t * D + kx];
                else            v = g_o0[(size_t)t * (HID * 32) + kx * 32 + b_];
            }
            s_act[idx] = v;
        }
        __syncthreads();

        // ================= GEMM partial: lane=batch, 8 j x 3 gates, f32x2 ========
        u64 aU[4], aR[4], aCH[4], aCX[4];
#pragma unroll
        for (int i = 0; i < 4; i++) { aU[i] = 0; aR[i] = 0; aCH[i] = 0; aCX[i] = 0; }

        const float* wp = WT + (size_t)k0 * G3 + j0;
        int kk = 0;
#pragma unroll 2
        for (; kk < hEnd; kk++, wp += G3) {            // hidden rows -> aCH
            u64 aa = packdup(s_act[kk * 32 + lane]);
            u64 w0,w1,w2,w3,w4,w5,w6,w7,w8,w9,wA,wB;
            ldw2(w0, w1, wp);
            ldw2(w2, w3, wp + 4);
            ldw2(w4, w5, wp + HID);
            ldw2(w6, w7, wp + HID + 4);
            ldw2(w8, w9, wp + 2 * HID);
            ldw2(wA, wB, wp + 2 * HID + 4);
            ffma2(aU[0], w0, aa);  ffma2(aU[1], w1, aa);
            ffma2(aU[2], w2, aa);  ffma2(aU[3], w3, aa);
            ffma2(aR[0], w4, aa);  ffma2(aR[1], w5, aa);
            ffma2(aR[2], w6, aa);  ffma2(aR[3], w7, aa);
            ffma2(aCH[0], w8, aa); ffma2(aCH[1], w9, aa);
            ffma2(aCH[2], wA, aa); ffma2(aCH[3], wB, aa);
        }
#pragma unroll 2
        for (; kk < CK; kk++, wp += G3) {              // x rows -> aCX
            u64 aa = packdup(s_act[kk * 32 + lane]);
            u64 w0,w1,w2,w3,w4,w5,w6,w7,w8,w9,wA,wB;
            ldw2(w0, w1, wp);
            ldw2(w2, w3, wp + 4);
            ldw2(w4, w5, wp + HID);
            ldw2(w6, w7, wp + HID + 4);
            ldw2(w8, w9, wp + 2 * HID);
            ldw2(wA, wB, wp + 2 * HID + 4);
            ffma2(aU[0], w0, aa);  ffma2(aU[1], w1, aa);
            ffma2(aU[2], w2, aa);  ffma2(aU[3], w3, aa);
            ffma2(aR[0], w4, aa);  ffma2(aR[1], w5, aa);
            ffma2(aR[2], w6, aa);  ffma2(aR[3], w7, aa);
            ffma2(aCX[0], w8, aa); ffma2(aCX[1], w9, aa);
            ffma2(aCX[2], wA, aa); ffma2(aCX[3], wB, aa);
        }

        // store partials: [kc][plane][j][b], coalesced over lane=b
        {
            float lo, hi;
            float* base = g_part + ((size_t)(kc * 4) * HID) * 32;
#pragma unroll
            for (int i = 0; i < 4; i++) {
                int jj = j0 + 2 * i;
                unpack2(aU[i], lo, hi);
                base[(0 * HID + jj) * 32 + lane] = lo;
                base[(0 * HID + jj + 1) * 32 + lane] = hi;
                unpack2(aR[i], lo, hi);
                base[(1 * HID + jj) * 32 + lane] = lo;
                base[(1 * HID + jj + 1) * 32 + lane] = hi;
            }
            if (hEnd > 0) {
#pragma unroll
                for (int i = 0; i < 4; i++) {
                    int jj = j0 + 2 * i;
                    unpack2(aCH[i], lo, hi);
                    base[(2 * HID + jj) * 32 + lane] = lo;
                    base[(2 * HID + jj + 1) * 32 + lane] = hi;
                }
            }
            if (hEnd < CK) {
#pragma unroll
                for (int i = 0; i < 4; i++) {
                    int jj = j0 + 2 * i;
                    unpack2(aCX[i], lo, hi);
                    base[(3 * HID + jj) * 32 + lane] = lo;
                    base[(3 * HID + jj + 1) * 32 + lane] = hi;
                }
            }
        }

        gbar(++gen);

        // ================= Phase B: elementwise EGRU update =================
        if (tid < 256) {
            float su = 0.f, sr = 0.f, sch = 0.f, scx = 0.f;
#pragma unroll
            for (int s = 0; s < KC; s++) {
                const float* q = g_part + ((size_t)(s * 4) * HID + fj) * 32 + fb;
                su += q[0];
                sr += q[(size_t)HID * 32];
                if (s < CH_HI) sch += q[(size_t)2 * HID * 32];
                if (s >= CX_LO) scx += q[(size_t)3 * HID * 32];
            }
            float iu = g_si[fj * 32 + fb];
            float ir = g_si[(HID + fj) * 32 + fb];
            float ic = g_si[(2 * HID + fj) * 32 + fb];

            float niu = ALPHA * iu + ONEMA * (su + bU);
            float u = sigmoidf_(niu);
            float nir = ALPHA * ir + ONEMA * (sr + bR);
            float r = sigmoidf_(nir);
            float nic = ALPHA * ic + ONEMA * (scx + r * sch + bC);
            float z = tanhf(nic);

            float cp = g_sc[fj * 32 + fb];
            float op = g_so[fj * 32 + fb];
            float creset = cp - op * thr;
            float nc = (1.0f - u) * creset + u * z;
            float no = (nc - thr > 0.0f) ? 1.0f : 0.0f;

            g_sc[fj * 32 + fb] = nc;
            g_so[fj * 32 + fb] = no;
            g_si[fj * 32 + fb] = niu;
            g_si[(HID + fj) * 32 + fb] = nir;
            g_si[(2 * HID + fj) * 32 + fb] = nic;

            if (LAYER == 0) {
                g_o0[(size_t)t * (HID * 32) + fj * 32 + fb] = no;
            } else {
                size_t ho = (size_t)t * (B * HID) + fb * HID + fj;
                hs[ho] = no * nc;
                cs[ho] = nc;
                os[ho] = no;
                size_t io = (size_t)t * (B * G3) + (size_t)fb * G3 + fj;
                is_[io] = niu;
                is_[io + HID] = nir;
                is_[io + 2 * HID] = nic;
            }
        }
        gbar(++gen);
    }
}

// ---------------- softmax head ----------------
__global__ void head_kernel(const float* __restrict__ hLast,
                            const float* __restrict__ w_out,
                            const float* __restrict__ b_out,
                            float* __restrict__ pred)
{
    __shared__ float sh_h[HID];
    __shared__ float red[OO];
    int b = blockIdx.x, tid = threadIdx.x;
    for (int i = tid; i < HID; i += OO) sh_h[i] = hLast[b * HID + i];
    __syncthreads();

    float acc = 0.0f;
    const float* w = w_out + (size_t)tid * HID;
#pragma unroll 4
    for (int k = 0; k < HID; k++) acc += w[k] * sh_h[k];
    float logit = acc + b_out[tid];

    red[tid] = logit; __syncthreads();
    for (int s = 128; s > 0; s >>= 1) { if (tid < s) red[tid] = fmaxf(red[tid], red[tid + s]); __syncthreads(); }
    float mx = red[0]; __syncthreads();
    float e = expf(logit - mx);
    red[tid] = e; __syncthreads();
    for (int s = 128; s > 0; s >>= 1) { if (tid < s) red[tid] += red[tid + s]; __syncthreads(); }
    float sum = red[0];
    pred[b * OO + tid] = e / sum;
}

// ---------------- launch ----------------
extern "C" void kernel_launch(void* const* d_in, const int* in_sizes, int n_in,
                              void* d_out, int out_size) {
    const float* x     = (const float*)d_in[0];
    const float* w_ih0 = (const float*)d_in[1];
    const float* w_hh0 = (const float*)d_in[2];
    const float* bias0 = (const float*)d_in[3];
    const float* thr0  = (const float*)d_in[4];
    const float* w_ih1 = (const float*)d_in[6];
    const float* w_hh1 = (const float*)d_in[7];
    const float* bias1 = (const float*)d_in[8];
    const float* thr1  = (const float*)d_in[9];
    const float* w_out = (const float*)d_in[11];
    const float* b_out = (const float*)d_in[12];

    float* out  = (float*)d_out;
    float* pred = out;
    float* hs   = out + B * OO;
    float* cs   = hs + (size_t)T * B * HID;
    float* os   = cs + (size_t)T * B * HID;
    float* is_  = os + (size_t)T * B * HID;

    dim3 tpt(32, 8);
    // layer-0 packs + scan first (puts scan<0> early in launch order for ncu -s 5)
    pack_kernel<<<dim3(HID / 32, G3 / 32), tpt>>>(w_hh0, 0, HID, 0);
    pack_kernel<<<dim3(D / 32, G3 / 32), tpt>>>(w_ih0, 0, D, HID);
    init_state_kernel<<<(B * G3 + 255) / 256, 256>>>();
    scan_kernel<0><<<NBLK, THR>>>(x, bias0, thr0, nullptr, nullptr, nullptr, nullptr);

    pack_kernel<<<dim3(HID / 32, G3 / 32), tpt>>>(w_hh1, 1, HID, 0);
    pack_kernel<<<dim3(HID / 32, G3 / 32), tpt>>>(w_ih1, 1, HID, HID);
    init_state_kernel<<<(B * G3 + 255) / 256, 256>>>();
    scan_kernel<1><<<NBLK, THR>>>(nullptr, bias1, thr1, hs, cs, os, is_);

    head_kernel<<<B, OO>>>(hs + (size_t)(T - 1) * B * HID, w_out, b_out, pred);
}

// round 5
// speedup vs baseline: 2.4893x; 1.6060x over previous
#include <cuda_runtime.h>
#include <math.h>

// Problem constants
#define B    32
#define T    256
#define D    256
#define HID  1024
#define G3   3072
#define OO   256
#define ALPHA 0.001f
#define ONEMA 0.999f

#define NBLK 128          // 8 jtiles x 16 kchunks; all resident
#define THR  512          // 16 warps
#define KC   16

typedef unsigned long long u64;

// ---------------- static device scratch (allocation-free) ----------------
__device__ float g_WT0[(HID + D) * G3];        // 1280 x 3072 k-major
__device__ float g_WT1[(2 * HID) * G3];        // 2048 x 3072 k-major
__device__ float g_o0[(size_t)T * B * HID];    // layer0 events, [t][b][j]
__device__ float g_sh[B * HID];                // h = o*c, [b][j]
__device__ float g_sc[B * HID];                // c state, [b][j]
__device__ float g_so[B * HID];                // o state, [b][j]
__device__ float g_si[B * G3];                 // i state, [b][col]
__device__ float g_part[(size_t)KC * 4 * B * HID];  // [kc][plane][b][j]
__device__ unsigned g_bar_cnt;
__device__ volatile unsigned g_bar_gen;

__device__ __forceinline__ float sigmoidf_(float v) { return 1.0f / (1.0f + expf(-v)); }

__device__ __forceinline__ void ffma2(u64& d, u64 a, u64 b) {
    asm("fma.rn.f32x2 %0, %1, %2, %0;" : "+l"(d) : "l"(a), "l"(b));
}
__device__ __forceinline__ u64 packdup(float a) {
    u64 r; unsigned ua = __float_as_uint(a);
    asm("mov.b64 %0, {%1, %1};" : "=l"(r) : "r"(ua));
    return r;
}
__device__ __forceinline__ void unpack2(u64 v, float& lo, float& hi) {
    unsigned l, h;
    asm("mov.b64 {%0, %1}, %2;" : "=r"(l), "=r"(h) : "l"(v));
    lo = __uint_as_float(l); hi = __uint_as_float(h);
}
__device__ __forceinline__ void lds2(u64& a, u64& b, unsigned addr) {
    asm volatile("ld.shared.v2.b64 {%0, %1}, [%2];" : "=l"(a), "=l"(b) : "r"(addr));
}

// ---------------- grid-wide barrier (all NBLK blocks resident) ----------------
__device__ __forceinline__ void gbar(unsigned target) {
    __syncthreads();
    if (threadIdx.x == 0) {
        __threadfence();
        unsigned old = atomicAdd(&g_bar_cnt, 1u);
        if (old == NBLK - 1u) {
            g_bar_cnt = 0u;
            __threadfence();
            g_bar_gen = target;
        } else {
            while (g_bar_gen != target) { }
        }
        __threadfence();
    }
    __syncthreads();
}

// ---------------- weight pack: dst[k][col] = src[col][k] ----------------
__global__ void pack_kernel(const float* __restrict__ src, int dstSel, int K, int rowOff) {
    __shared__ float tile[32][33];
    float* dst = dstSel ? g_WT1 : g_WT0;
    int kBase = blockIdx.x * 32;
    int colBase = blockIdx.y * 32;
    int tx = threadIdx.x, ty = threadIdx.y;   // (32, 8)
#pragma unroll
    for (int i = 0; i < 32; i += 8) {
        int col = colBase + ty + i;
        tile[ty + i][tx] = src[(size_t)col * K + kBase + tx];
    }
    __syncthreads();
#pragma unroll
    for (int i = 0; i < 32; i += 8) {
        int k = kBase + ty + i;
        dst[(size_t)(k + rowOff) * G3 + colBase + tx] = tile[tx][ty + i];
    }
}

// ---------------- state + barrier init ----------------
__global__ void init_state_kernel() {
    int idx = blockIdx.x * blockDim.x + threadIdx.x;
    if (idx < B * HID) { g_sc[idx] = 0.0f; g_so[idx] = 0.0f; g_sh[idx] = 0.0f; }
    if (idx < B * G3) g_si[idx] = 0.0f;
    if (idx == 0) { g_bar_cnt = 0u; g_bar_gen = 0u; }
}

// ---------------- persistent scan kernel ----------------
// grid = 128 blocks (bid>>4 = jtile of 128 j, bid&15 = kchunk), 512 threads.
// Weights staged in SMEM once; inner loop is LDS + f32x2 FMA only.
template <int LAYER>
__global__ __launch_bounds__(THR, 1) void scan_kernel(
    const float* __restrict__ x,
    const float* __restrict__ bias,
    const float* __restrict__ thr_raw,
    float* __restrict__ hs, float* __restrict__ cs,
    float* __restrict__ os, float* __restrict__ is_)
{
    constexpr int CK    = (LAYER == 0) ? 80 : 128;   // K tot 1280 / 2048, 16 chunks
    constexpr int CH_HI = (LAYER == 0) ? 13 : 8;     // chunks with hidden rows
    constexpr int CX_LO = (LAYER == 0) ? 12 : 8;     // chunks with x rows
    const float* __restrict__ WT = (LAYER == 0) ? g_WT0 : g_WT1;

    extern __shared__ float smem[];
    float* s_w   = smem;                      // [CK][3][128]
    float* s_act = smem + CK * 3 * 128;       // [CK][33] padded

    const int tid  = threadIdx.x;
    const int lane = tid & 31;                // = batch in GEMM phase
    const int wrp  = tid >> 5;
    const int kc   = blockIdx.x & 15;
    const int jt   = blockIdx.x >> 4;
    const int k0   = kc * CK;
    const int jbase = jt * 128;
    const int j0w  = wrp * 8;                 // warp's j offset within tile

    int hEnd = HID - k0;
    if (hEnd < 0) hEnd = 0;
    if (hEnd > CK) hEnd = CK;

    // ---- stage weights into smem ONCE (constant across all timesteps) ----
    for (int i = tid; i < CK * 3 * 32; i += THR) {      // float4 granularity
        int lin = i * 4;
        int kk = lin / 384;
        int r = lin - kk * 384;
        int g = r >> 7;
        int jj = r & 127;
        float4 v = *(const float4*)(WT + (size_t)(k0 + kk) * G3 + g * HID + jbase + jj);
        *(float4*)(s_w + kk * 384 + g * 128 + jj) = v;
    }

    // phase-B mapping: 256 threads/block, j-fastest (all IO coalesced)
    const int fidx = blockIdx.x * 256 + tid;            // = fb*1024 + fj
    const int fb = fidx >> 10;
    const int fj = fidx & 1023;
    float thv = 0.f, bU = 0.f, bR = 0.f, bC = 0.f;
    if (tid < 256) {
        thv = sigmoidf_(thr_raw[fj]);
        bU = bias[fj]; bR = bias[HID + fj]; bC = bias[2 * HID + fj];
    }
    __syncthreads();

    const unsigned wbase_u = (unsigned)__cvta_generic_to_shared(s_w) + j0w * 4;

    unsigned gen = 0;

    for (int t = 0; t < T; t++) {
        // ---- stage activations for this chunk ----
        for (int i = tid; i < CK * 32; i += THR) {
            int b_ = i / CK;
            int kk = i - b_ * CK;
            int kg = k0 + kk;
            float v;
            if (kg < HID) {
                v = g_sh[b_ * HID + kg];
            } else {
                int kx = kg - HID;
                if (LAYER == 0) v = x[(size_t)b_ * (T * D) + t * D + kx];
                else            v = g_o0[(size_t)t * (B * HID) + b_ * HID + kx];
            }
            s_act[kk * 33 + b_] = v;
        }
        __syncthreads();

        // ---- GEMM partial: lane=batch, 8 j x 3 gates, pure LDS + f32x2 ----
        u64 aU[4], aR[4], aCH[4], aCX[4];
#pragma unroll
        for (int i = 0; i < 4; i++) { aU[i] = 0; aR[i] = 0; aCH[i] = 0; aCX[i] = 0; }

        int kk = 0;
#pragma unroll 2
        for (; kk < hEnd; kk++) {             // hidden rows -> aCH
            u64 aa = packdup(s_act[kk * 33 + lane]);
            unsigned wa = wbase_u + kk * 1536;
            u64 w0,w1,w2,w3,w4,w5,w6,w7,w8,w9,wA,wB;
            lds2(w0, w1, wa);        lds2(w2, w3, wa + 16);
            lds2(w4, w5, wa + 512);  lds2(w6, w7, wa + 528);
            lds2(w8, w9, wa + 1024); lds2(wA, wB, wa + 1040);
            ffma2(aU[0], w0, aa);  ffma2(aU[1], w1, aa);
            ffma2(aU[2], w2, aa);  ffma2(aU[3], w3, aa);
            ffma2(aR[0], w4, aa);  ffma2(aR[1], w5, aa);
            ffma2(aR[2], w6, aa);  ffma2(aR[3], w7, aa);
            ffma2(aCH[0], w8, aa); ffma2(aCH[1], w9, aa);
            ffma2(aCH[2], wA, aa); ffma2(aCH[3], wB, aa);
        }
#pragma unroll 2
        for (; kk < CK; kk++) {               // x rows -> aCX
            u64 aa = packdup(s_act[kk * 33 + lane]);
            unsigned wa = wbase_u + kk * 1536;
            u64 w0,w1,w2,w3,w4,w5,w6,w7,w8,w9,wA,wB;
            lds2(w0, w1, wa);        lds2(w2, w3, wa + 16);
            lds2(w4, w5, wa + 512);  lds2(w6, w7, wa + 528);
            lds2(w8, w9, wa + 1024); lds2(wA, wB, wa + 1040);
            ffma2(aU[0], w0, aa);  ffma2(aU[1], w1, aa);
            ffma2(aU[2], w2, aa);  ffma2(aU[3], w3, aa);
            ffma2(aR[0], w4, aa);  ffma2(aR[1], w5, aa);
            ffma2(aR[2], w6, aa);  ffma2(aR[3], w7, aa);
            ffma2(aCX[0], w8, aa); ffma2(aCX[1], w9, aa);
            ffma2(aCX[2], wA, aa); ffma2(aCX[3], wB, aa);
        }

        // ---- store partials [kc][plane][b=lane][j], 2x float4 per plane ----
        {
            float f[8];
            const size_t PL = (size_t)32 * HID;           // plane stride
            float* pb = g_part + ((size_t)(kc * 4) * 32 + lane) * HID + jbase + j0w;
#pragma unroll
            for (int i = 0; i < 4; i++) unpack2(aU[i], f[2*i], f[2*i+1]);
            *(float4*)(pb)     = make_float4(f[0], f[1], f[2], f[3]);
            *(float4*)(pb + 4) = make_float4(f[4], f[5], f[6], f[7]);
#pragma unroll
            for (int i = 0; i < 4; i++) unpack2(aR[i], f[2*i], f[2*i+1]);
            *(float4*)(pb + PL)     = make_float4(f[0], f[1], f[2], f[3]);
            *(float4*)(pb + PL + 4) = make_float4(f[4], f[5], f[6], f[7]);
            if (hEnd > 0) {
#pragma unroll
                for (int i = 0; i < 4; i++) unpack2(aCH[i], f[2*i], f[2*i+1]);
                *(float4*)(pb + 2 * PL)     = make_float4(f[0], f[1], f[2], f[3]);
                *(float4*)(pb + 2 * PL + 4) = make_float4(f[4], f[5], f[6], f[7]);
            }
            if (hEnd < CK) {
#pragma unroll
                for (int i = 0; i < 4; i++) unpack2(aCX[i], f[2*i], f[2*i+1]);
                *(float4*)(pb + 3 * PL)     = make_float4(f[0], f[1], f[2], f[3]);
                *(float4*)(pb + 3 * PL + 4) = make_float4(f[4], f[5], f[6], f[7]);
            }
        }

        gbar(++gen);

        // ---- Phase B: elementwise EGRU update (coalesced, j-fastest) ----
        if (tid < 256) {
            const size_t PL = (size_t)32 * HID;
            float su = 0.f, sr = 0.f, sch = 0.f, scx = 0.f;
#pragma unroll
            for (int s = 0; s < KC; s++) {
                const float* q = g_part + ((size_t)(s * 4) * 32 + fb) * HID + fj;
                su += q[0];
                sr += q[PL];
                if (s < CH_HI) sch += q[2 * PL];
                if (s >= CX_LO) scx += q[3 * PL];
            }
            float iu = g_si[fb * G3 + fj];
            float ir = g_si[fb * G3 + HID + fj];
            float ic = g_si[fb * G3 + 2 * HID + fj];

            float niu = ALPHA * iu + ONEMA * (su + bU);
            float u = sigmoidf_(niu);
            float nir = ALPHA * ir + ONEMA * (sr + bR);
            float r = sigmoidf_(nir);
            float nic = ALPHA * ic + ONEMA * (scx + r * sch + bC);
            float z = tanhf(nic);

            float cp = g_sc[fb * HID + fj];
            float op = g_so[fb * HID + fj];
            float creset = cp - op * thv;
            float nc = (1.0f - u) * creset + u * z;
            float no = (nc - thv > 0.0f) ? 1.0f : 0.0f;

            g_sc[fb * HID + fj] = nc;
            g_so[fb * HID + fj] = no;
            g_sh[fb * HID + fj] = no * nc;
            g_si[fb * G3 + fj] = niu;
            g_si[fb * G3 + HID + fj] = nir;
            g_si[fb * G3 + 2 * HID + fj] = nic;

            if (LAYER == 0) {
                g_o0[(size_t)t * (B * HID) + fb * HID + fj] = no;
            } else {
                size_t ho = (size_t)t * (B * HID) + fb * HID + fj;
                hs[ho] = no * nc;
                cs[ho] = nc;
                os[ho] = no;
                size_t io = (size_t)t * (B * G3) + (size_t)fb * G3 + fj;
                is_[io] = niu;
                is_[io + HID] = nir;
                is_[io + 2 * HID] = nic;
            }
        }
        gbar(++gen);
    }
}

// ---------------- softmax head ----------------
__global__ void head_kernel(const float* __restrict__ hLast,
                            const float* __restrict__ w_out,
                            const float* __restrict__ b_out,
                            float* __restrict__ pred)
{
    __shared__ float sh_h[HID];
    __shared__ float red[OO];
    int b = blockIdx.x, tid = threadIdx.x;
    for (int i = tid; i < HID; i += OO) sh_h[i] = hLast[b * HID + i];
    __syncthreads();

    float acc = 0.0f;
    const float* w = w_out + (size_t)tid * HID;
#pragma unroll 4
    for (int k = 0; k < HID; k++) acc += w[k] * sh_h[k];
    float logit = acc + b_out[tid];

    red[tid] = logit; __syncthreads();
    for (int s = 128; s > 0; s >>= 1) { if (tid < s) red[tid] = fmaxf(red[tid], red[tid + s]); __syncthreads(); }
    float mx = red[0]; __syncthreads();
    float e = expf(logit - mx);
    red[tid] = e; __syncthreads();
    for (int s = 128; s > 0; s >>= 1) { if (tid < s) red[tid] += red[tid + s]; __syncthreads(); }
    float sum = red[0];
    pred[b * OO + tid] = e / sum;
}

// ---------------- launch ----------------
extern "C" void kernel_launch(void* const* d_in, const int* in_sizes, int n_in,
                              void* d_out, int out_size) {
    const float* x     = (const float*)d_in[0];
    const float* w_ih0 = (const float*)d_in[1];
    const float* w_hh0 = (const float*)d_in[2];
    const float* bias0 = (const float*)d_in[3];
    const float* thr0  = (const float*)d_in[4];
    const float* w_ih1 = (const float*)d_in[6];
    const float* w_hh1 = (const float*)d_in[7];
    const float* bias1 = (const float*)d_in[8];
    const float* thr1  = (const float*)d_in[9];
    const float* w_out = (const float*)d_in[11];
    const float* b_out = (const float*)d_in[12];

    float* out  = (float*)d_out;
    float* pred = out;
    float* hs   = out + B * OO;
    float* cs   = hs + (size_t)T * B * HID;
    float* os   = cs + (size_t)T * B * HID;
    float* is_  = os + (size_t)T * B * HID;

    const int SMEM0 = (80 * 3 * 128 + 80 * 33) * 4;     // 133,440 B
    const int SMEM1 = (128 * 3 * 128 + 128 * 33) * 4;   // 213,504 B
    cudaFuncSetAttribute(scan_kernel<0>, cudaFuncAttributeMaxDynamicSharedMemorySize, SMEM0);
    cudaFuncSetAttribute(scan_kernel<1>, cudaFuncAttributeMaxDynamicSharedMemorySize, SMEM1);

    dim3 tpt(32, 8);
    pack_kernel<<<dim3(HID / 32, G3 / 32), tpt>>>(w_hh0, 0, HID, 0);
    pack_kernel<<<dim3(D / 32, G3 / 32), tpt>>>(w_ih0, 0, D, HID);
    init_state_kernel<<<(B * G3 + 255) / 256, 256>>>();
    scan_kernel<0><<<NBLK, THR, SMEM0>>>(x, bias0, thr0, nullptr, nullptr, nullptr, nullptr);

    pack_kernel<<<dim3(HID / 32, G3 / 32), tpt>>>(w_hh1, 1, HID, 0);
    pack_kernel<<<dim3(HID / 32, G3 / 32), tpt>>>(w_ih1, 1, HID, HID);
    init_state_kernel<<<(B * G3 + 255) / 256, 256>>>();
    scan_kernel<1><<<NBLK, THR, SMEM1>>>(nullptr, bias1, thr1, hs, cs, os, is_);

    head_kernel<<<B, OO>>>(hs + (size_t)(T - 1) * B * HID, w_out, b_out, pred);
}

// round 8
// speedup vs baseline: 3.1611x; 1.2699x over previous
#include <cuda_runtime.h>
#include <math.h>

// Problem constants
#define B    32
#define T    256
#define D    256
#define HID  1024
#define G3   3072
#define OO   256
#define ALPHA 0.001f
#define ONEMA 0.999f

#define NBLK 128          // one block per 8 output columns (128*8 = 1024)
#define THR  512          // 16 warps = 16 k-chunks

typedef unsigned long long u64;

// ---------------- static device scratch (allocation-free) ----------------
__device__ float g_WT0[(HID + D) * G3];        // 1280 x 3072 k-major
__device__ float g_WT1[(2 * HID) * G3];        // 2048 x 3072 k-major
__device__ float g_xT[(size_t)T * D * 32];     // transposed input [t*D+d][b]
__device__ float g_o0[(size_t)T * HID * 32];   // layer0 events [t][j][b]
__device__ float g_sh[2][HID * 32];            // h = o*c, [j][b], double-buffered
__device__ float g_sc[B * HID];                // c state, [b][j]
__device__ float g_so[B * HID];                // o state, [b][j]
__device__ float g_si[B * G3];                 // i state, [b][col]
__device__ unsigned g_bar_cnt;
__device__ volatile unsigned g_bar_gen;

__device__ __forceinline__ float sigmoidf_(float v) { return 1.0f / (1.0f + expf(-v)); }

__device__ __forceinline__ void ffma2(u64& d, u64 a, u64 b) {
    asm("fma.rn.f32x2 %0, %1, %2, %0;" : "+l"(d) : "l"(a), "l"(b));
}
__device__ __forceinline__ u64 packdup(float a) {
    u64 r; unsigned ua = __float_as_uint(a);
    asm("mov.b64 %0, {%1, %1};" : "=l"(r) : "r"(ua));
    return r;
}
__device__ __forceinline__ void unpack2(u64 v, float& lo, float& hi) {
    unsigned l, h;
    asm("mov.b64 {%0, %1}, %2;" : "=r"(l), "=r"(h) : "l"(v));
    lo = __uint_as_float(l); hi = __uint_as_float(h);
}

// ---------------- grid-wide barrier (all NBLK blocks resident) ----------------
__device__ __forceinline__ void gbar(unsigned target) {
    __syncthreads();
    if (threadIdx.x == 0) {
        __threadfence();
        unsigned old = atomicAdd(&g_bar_cnt, 1u);
        if (old == NBLK - 1u) {
            g_bar_cnt = 0u;
            __threadfence();
            g_bar_gen = target;
        } else {
            while (g_bar_gen != target) { }
        }
        __threadfence();
    }
    __syncthreads();
}

// ---------------- weight pack: dst[k][col] = src[col][k] ----------------
__global__ void pack_kernel(const float* __restrict__ src, int dstSel, int K, int rowOff) {
    __shared__ float tile[32][33];
    float* dst = dstSel ? g_WT1 : g_WT0;
    int kBase = blockIdx.x * 32;
    int colBase = blockIdx.y * 32;
    int tx = threadIdx.x, ty = threadIdx.y;   // (32, 8)
#pragma unroll
    for (int i = 0; i < 32; i += 8) {
        int col = colBase + ty + i;
        tile[ty + i][tx] = src[(size_t)col * K + kBase + tx];
    }
    __syncthreads();
#pragma unroll
    for (int i = 0; i < 32; i += 8) {
        int k = kBase + ty + i;
        dst[(size_t)(k + rowOff) * G3 + colBase + tx] = tile[tx][ty + i];
    }
}

// ---------------- x transpose: x[b][t][d] -> g_xT[t*D+d][b] ----------------
__global__ void xpose_kernel(const float* __restrict__ x) {
    __shared__ float tile[32][33];
    int col0 = blockIdx.x * 32;               // td tile
    int tx = threadIdx.x, ty = threadIdx.y;   // (32, 8)
#pragma unroll
    for (int i = 0; i < 32; i += 8) {
        int b = ty + i;
        tile[b][tx] = x[(size_t)b * (T * D) + col0 + tx];
    }
    __syncthreads();
#pragma unroll
    for (int i = 0; i < 32; i += 8) {
        int td = col0 + ty + i;
        g_xT[(size_t)td * 32 + tx] = tile[tx][ty + i];
    }
}

// ---------------- state + barrier init ----------------
__global__ void init_state_kernel() {
    int idx = blockIdx.x * blockDim.x + threadIdx.x;
    if (idx < B * HID) {
        g_sc[idx] = 0.0f; g_so[idx] = 0.0f;
        g_sh[0][idx] = 0.0f; g_sh[1][idx] = 0.0f;
    }
    if (idx < B * G3) g_si[idx] = 0.0f;
    if (idx == 0) { g_bar_cnt = 0u; g_bar_gen = 0u; }
}

// store one gate's 8-j partial (4 u64 pairs) into exchange buffer, pitch 9
__device__ __forceinline__ void store8(float* s_p, int wrp, int lane, const u64* a) {
    float* p = s_p + (wrp * 32 + lane) * 9;
    float lo, hi;
    unpack2(a[0], lo, hi); p[0] = lo; p[1] = hi;
    unpack2(a[1], lo, hi); p[2] = lo; p[3] = hi;
    unpack2(a[2], lo, hi); p[4] = lo; p[5] = hi;
    unpack2(a[3], lo, hi); p[6] = lo; p[7] = hi;
}

// ---------------- persistent scan kernel ----------------
// grid = 128 blocks, each owns 8 j-columns; warp w = contiguous k-chunk w
// (CK = KT/16 — identical chunking to the round-5 passing kernel).
// Cross-chunk sums are done serially in chunk order s=0..15 by the update
// threads (bitwise identical to round 5's accumulation). One gbar/step.
template <int LAYER>
__global__ __launch_bounds__(THR, 1) void scan_kernel(
    const float* __restrict__ bias,
    const float* __restrict__ thr_raw,
    float* __restrict__ hs, float* __restrict__ cs,
    float* __restrict__ os, float* __restrict__ is_)
{
    constexpr int KX    = (LAYER == 0) ? D : HID;    // x-part K
    constexpr int KT    = HID + KX;                  // total K
    constexpr int CK    = KT / 16;                   // 80 / 128 per warp-chunk
    constexpr int CH_HI = (LAYER == 0) ? 13 : 8;     // chunks with hidden rows
    constexpr int CX_LO = (LAYER == 0) ? 12 : 8;     // chunks with x rows
    const float* __restrict__ WT = (LAYER == 0) ? g_WT0 : g_WT1;

    extern __shared__ float smem[];
    float* s_w = smem;                               // [KT][24]
    float* s_p = smem + KT * 24;                     // [16][32][9] exchange

    const int tid  = threadIdx.x;
    const int lane = tid & 31;                       // = batch in GEMM
    const int wrp  = tid >> 5;                       // = k-chunk index
    const int jb   = blockIdx.x * 8;                 // block's 8 j-columns

    // ---- stage weights into smem once ----
    for (int i = tid; i < KT * 6; i += THR) {
        int k = i / 6, c = i - k * 6;
        int g = c >> 1, half = c & 1;
        float4 v = *(const float4*)(WT + (size_t)k * G3 + g * HID + jb + half * 4);
        ((float4*)(s_w + k * 24))[c] = v;
    }

    // update-phase constants (tid<256: fj = tid&7, fb = tid>>3)
    const int fj = tid & 7;
    const int fb = tid >> 3;
    const int jg = jb + fj;
    float thv = 0.f, bU = 0.f, bR = 0.f, bC = 0.f;
    if (tid < 256) {
        thv = sigmoidf_(thr_raw[jg]);
        bU = bias[jg]; bR = bias[HID + jg]; bC = bias[2 * HID + jg];
    }
    __syncthreads();

    const int k0 = wrp * CK;
    int hEnd = HID - k0;                             // hidden rows in this chunk
    if (hEnd < 0) hEnd = 0;
    if (hEnd > CK) hEnd = CK;
    const int xCnt = CK - hEnd;
    const int kx0 = k0 + hEnd - HID;                 // x-row start (valid iff xCnt>0)

    unsigned gen = 0;

    for (int t = 0; t < T; t++) {
        const float* __restrict__ shR = g_sh[t & 1];
        float* __restrict__ shW = g_sh[(t & 1) ^ 1];

        // ---- GEMM: serial over this warp's contiguous chunk (round-5 order) ----
        u64 aU[4], aR[4], aCH[4], aCX[4];
#pragma unroll
        for (int i = 0; i < 4; i++) { aU[i] = 0; aR[i] = 0; aCH[i] = 0; aCX[i] = 0; }

        const longlong2* wr = (const longlong2*)(s_w + (size_t)k0 * 24);
        {   // hidden rows -> aCH
            const float* ah = shR + (size_t)k0 * 32 + lane;
#pragma unroll 4
            for (int kk = 0; kk < hEnd; kk++) {
                u64 aa = packdup(ah[kk * 32]);
                longlong2 p0 = wr[0], p1 = wr[1], p2 = wr[2];
                longlong2 p3 = wr[3], p4 = wr[4], p5 = wr[5];
                ffma2(aU[0], (u64)p0.x, aa); ffma2(aU[1], (u64)p0.y, aa);
                ffma2(aU[2], (u64)p1.x, aa); ffma2(aU[3], (u64)p1.y, aa);
                ffma2(aR[0], (u64)p2.x, aa); ffma2(aR[1], (u64)p2.y, aa);
                ffma2(aR[2], (u64)p3.x, aa); ffma2(aR[3], (u64)p3.y, aa);
                ffma2(aCH[0], (u64)p4.x, aa); ffma2(aCH[1], (u64)p4.y, aa);
                ffma2(aCH[2], (u64)p5.x, aa); ffma2(aCH[3], (u64)p5.y, aa);
                wr += 6;
            }
        }
        {   // x rows -> aCX
            const float* ax = (LAYER == 0)
                ? g_xT + ((size_t)t * D + kx0) * 32 + lane
                : g_o0 + ((size_t)t * HID + kx0) * 32 + lane;
#pragma unroll 4
            for (int kk = 0; kk < xCnt; kk++) {
                u64 aa = packdup(ax[kk * 32]);
                longlong2 p0 = wr[0], p1 = wr[1], p2 = wr[2];
                longlong2 p3 = wr[3], p4 = wr[4], p5 = wr[5];
                ffma2(aU[0], (u64)p0.x, aa); ffma2(aU[1], (u64)p0.y, aa);
                ffma2(aU[2], (u64)p1.x, aa); ffma2(aU[3], (u64)p1.y, aa);
                ffma2(aR[0], (u64)p2.x, aa); ffma2(aR[1], (u64)p2.y, aa);
                ffma2(aR[2], (u64)p3.x, aa); ffma2(aR[3], (u64)p3.y, aa);
                ffma2(aCX[0], (u64)p4.x, aa); ffma2(aCX[1], (u64)p4.y, aa);
                ffma2(aCX[2], (u64)p5.x, aa); ffma2(aCX[3], (u64)p5.y, aa);
                wr += 6;
            }
        }

        // ---- gate-by-gate exchange; serial chunk-order sums (round-5 bitwise) ----
        float su = 0.f, sr = 0.f, sch = 0.f, scx = 0.f;

        store8(s_p, wrp, lane, aU);
        __syncthreads();
        if (tid < 256) {
#pragma unroll
            for (int s = 0; s < 16; s++) su += s_p[(s * 32 + fb) * 9 + fj];
        }
        __syncthreads();

        store8(s_p, wrp, lane, aR);
        __syncthreads();
        if (tid < 256) {
#pragma unroll
            for (int s = 0; s < 16; s++) sr += s_p[(s * 32 + fb) * 9 + fj];
        }
        __syncthreads();

        store8(s_p, wrp, lane, aCH);
        __syncthreads();
        if (tid < 256) {
#pragma unroll
            for (int s = 0; s < 16; s++)
                if (s < CH_HI) sch += s_p[(s * 32 + fb) * 9 + fj];
        }
        __syncthreads();

        store8(s_p, wrp, lane, aCX);
        __syncthreads();
        if (tid < 256) {
#pragma unroll
            for (int s = 0; s < 16; s++)
                if (s >= CX_LO) scx += s_p[(s * 32 + fb) * 9 + fj];
        }

        // ---- EGRU update: 256 threads, one (b, j) each ----
        if (tid < 256) {
            float iu = g_si[fb * G3 + jg];
            float ir = g_si[fb * G3 + HID + jg];
            float ic = g_si[fb * G3 + 2 * HID + jg];

            float niu = ALPHA * iu + ONEMA * (su + bU);
            float u = sigmoidf_(niu);
            float nir = ALPHA * ir + ONEMA * (sr + bR);
            float r = sigmoidf_(nir);
            float nic = ALPHA * ic + ONEMA * (scx + r * sch + bC);
            float z = tanhf(nic);

            float cp = g_sc[fb * HID + jg];
            float op = g_so[fb * HID + jg];
            float creset = cp - op * thv;
            float nc = (1.0f - u) * creset + u * z;
            float no = (nc - thv > 0.0f) ? 1.0f : 0.0f;

            g_sc[fb * HID + jg] = nc;
            g_so[fb * HID + jg] = no;
            shW[jg * 32 + fb] = no * nc;
            g_si[fb * G3 + jg] = niu;
            g_si[fb * G3 + HID + jg] = nir;
            g_si[fb * G3 + 2 * HID + jg] = nic;

            if (LAYER == 0) {
                g_o0[((size_t)t * HID + jg) * 32 + fb] = no;
            } else {
                size_t ho = (size_t)t * (B * HID) + fb * HID + jg;
                hs[ho] = no * nc;
                cs[ho] = nc;
                os[ho] = no;
                size_t io = (size_t)t * (B * G3) + (size_t)fb * G3 + jg;
                is_[io] = niu;
                is_[io + HID] = nir;
                is_[io + 2 * HID] = nic;
            }
        }
        gbar(++gen);
    }
}

// ---------------- softmax head ----------------
__global__ void head_kernel(const float* __restrict__ hLast,
                            const float* __restrict__ w_out,
                            const float* __restrict__ b_out,
                            float* __restrict__ pred)
{
    __shared__ float sh_h[HID];
    __shared__ float red[OO];
    int b = blockIdx.x, tid = threadIdx.x;
    for (int i = tid; i < HID; i += OO) sh_h[i] = hLast[b * HID + i];
    __syncthreads();

    float acc = 0.0f;
    const float* w = w_out + (size_t)tid * HID;
#pragma unroll 4
    for (int k = 0; k < HID; k++) acc += w[k] * sh_h[k];
    float logit = acc + b_out[tid];

    red[tid] = logit; __syncthreads();
    for (int s = 128; s > 0; s >>= 1) { if (tid < s) red[tid] = fmaxf(red[tid], red[tid + s]); __syncthreads(); }
    float mx = red[0]; __syncthreads();
    float e = expf(logit - mx);
    red[tid] = e; __syncthreads();
    for (int s = 128; s > 0; s >>= 1) { if (tid < s) red[tid] += red[tid + s]; __syncthreads(); }
    float sum = red[0];
    pred[b * OO + tid] = e / sum;
}

// ---------------- launch ----------------
extern "C" void kernel_launch(void* const* d_in, const int* in_sizes, int n_in,
                              void* d_out, int out_size) {
    const float* x     = (const float*)d_in[0];
    const float* w_ih0 = (const float*)d_in[1];
    const float* w_hh0 = (const float*)d_in[2];
    const float* bias0 = (const float*)d_in[3];
    const float* thr0  = (const float*)d_in[4];
    const float* w_ih1 = (const float*)d_in[6];
    const float* w_hh1 = (const float*)d_in[7];
    const float* bias1 = (const float*)d_in[8];
    const float* thr1  = (const float*)d_in[9];
    const float* w_out = (const float*)d_in[11];
    const float* b_out = (const float*)d_in[12];

    float* out  = (float*)d_out;
    float* pred = out;
    float* hs   = out + B * OO;
    float* cs   = hs + (size_t)T * B * HID;
    float* os   = cs + (size_t)T * B * HID;
    float* is_  = os + (size_t)T * B * HID;

    const int SMEM0 = (HID + D) * 24 * 4 + 16 * 32 * 9 * 4;     // 141,312 B
    const int SMEM1 = (2 * HID) * 24 * 4 + 16 * 32 * 9 * 4;     // 215,040 B
    cudaFuncSetAttribute(scan_kernel<0>, cudaFuncAttributeMaxDynamicSharedMemorySize, SMEM0);
    cudaFuncSetAttribute(scan_kernel<1>, cudaFuncAttributeMaxDynamicSharedMemorySize, SMEM1);

    dim3 tpt(32, 8);
    pack_kernel<<<dim3(HID / 32, G3 / 32), tpt>>>(w_hh0, 0, HID, 0);
    pack_kernel<<<dim3(D / 32, G3 / 32), tpt>>>(w_ih0, 0, D, HID);
    xpose_kernel<<<T * D / 32, tpt>>>(x);
    init_state_kernel<<<(B * G3 + 255) / 256, 256>>>();
    scan_kernel<0><<<NBLK, THR, SMEM0>>>(bias0, thr0, nullptr, nullptr, nullptr, nullptr);

    pack_kernel<<<dim3(HID / 32, G3 / 32), tpt>>>(w_hh1, 1, HID, 0);
    pack_kernel<<<dim3(HID / 32, G3 / 32), tpt>>>(w_ih1, 1, HID, HID);
    init_state_kernel<<<(B * G3 + 255) / 256, 256>>>();
    scan_kernel<1><<<NBLK, THR, SMEM1>>>(bias1, thr1, hs, cs, os, is_);

    head_kernel<<<B, OO>>>(hs + (size_t)(T - 1) * B * HID, w_out, b_out, pred);
}